// round 6
// baseline (speedup 1.0000x reference)
#include <cuda_runtime.h>
#include <cstdint>

#define N_   8
#define C_   64
#define H_   256
#define W_   256
#define G_   8
#define CPG_ 8               // channels per group
#define ROWS 8               // rows per block strip
#define TR   (ROWS+2)        // tile rows incl. halo
#define CHUNKS (H_/ROWS)     // 32
#define EPS_ 1e-5f
#define NT   256
#define W4_  (W_/4)          // 64
#define TQ   (TR*W4_)        // 640 float4 per tile
#define HWQ  (H_*W_/4)       // 16384 quads per plane
#define CHPB 8               // channels per pass2b block (C_/8)

// Static scratch (no runtime allocation)
__device__ float g_part[N_*G_*CHUNKS*2];
__device__ float g_esum[(size_t)N_*G_*H_*W_];      // per-(n,g) sum of exp (16.8 MB)

__device__ __forceinline__ float tanh_fast(float x) {
    float y;
    asm("tanh.approx.f32 %0, %1;" : "=f"(y) : "f"(x));
    return y;
}

#define CP_COMMIT() asm volatile("cp.async.commit_group;")
#define CP_WAIT1()  asm volatile("cp.async.wait_group 1;")

// Stage one (TR x W_) channel tile gmem -> smem via cp.async.cg.
__device__ __forceinline__ void cpa_tile(unsigned sbase, const float4* __restrict__ xc4,
                                         int h0, int tid) {
    #pragma unroll
    for (int i = 0; i < 3; ++i) {
        const int idx = tid + i*NT;
        if (idx < TQ) {
            const int r = idx >> 6, q = idx & (W4_-1);
            const int h = h0 - 1 + r;
            const bool v = (h >= 0) && (h < H_);
            const float4* src = xc4 + (v ? (h*W4_ + q) : q);   // clamped (unread if sz=0)
            const int sz = v ? 16 : 0;
            asm volatile("cp.async.cg.shared.global [%0], [%1], 16, %2;"
                         :: "r"(sbase + (unsigned)idx*16u), "l"(src), "r"(sz));
        }
    }
}

// 3x3 depthwise conv over the strip for this thread's column; SINK sees (r, conv).
#define CONV_STRIP(tile, wk, SINK)                                        \
    {                                                                     \
        float L0 = hasL ? (tile)[tid-1]    : 0.f;                         \
        float M0 =        (tile)[tid];                                    \
        float R0 = hasR ? (tile)[tid+1]    : 0.f;                         \
        float L1 = hasL ? (tile)[W_+tid-1] : 0.f;                         \
        float M1 =        (tile)[W_+tid];                                 \
        float R1 = hasR ? (tile)[W_+tid+1] : 0.f;                         \
        _Pragma("unroll")                                                 \
        for (int r = 0; r < ROWS; ++r) {                                  \
            const float* row2 = (tile) + (r+2)*W_;                        \
            const float L2 = hasL ? row2[tid-1] : 0.f;                    \
            const float M2 =        row2[tid];                            \
            const float R2 = hasR ? row2[tid+1] : 0.f;                    \
            float conv =        L0*wk[0];                                 \
            conv = fmaf(M0, wk[1], conv); conv = fmaf(R0, wk[2], conv);   \
            conv = fmaf(L1, wk[3], conv); conv = fmaf(M1, wk[4], conv);   \
            conv = fmaf(R1, wk[5], conv); conv = fmaf(L2, wk[6], conv);   \
            conv = fmaf(M2, wk[7], conv); conv = fmaf(R2, wk[8], conv);   \
            SINK;                                                         \
            L0=L1; M0=M1; R0=R1; L1=L2; M1=M2; R1=R2;                     \
        }                                                                 \
    }

// One pipelined stage: pass1(img k) | pass2a(img k-1) | pass2b(img k-2).
// Launch boundary between stages provides the stats / esum barriers.
__global__ __launch_bounds__(NT) void k_stage(int k,
                                              const float* __restrict__ x,
                                              const float* __restrict__ wgt,
                                              float* __restrict__ out) {
    __shared__ float4 buf[3][TQ];                   // 30.7 KB triple buffer
    __shared__ float  wsm[9][CPG_];
    __shared__ float  red[8], red2[8];
    __shared__ float  s_stats[2];                   // mean, rstd

    const int bid = blockIdx.x;
    const int tid = threadIdx.x;
    const int lane = tid & 31, wid = tid >> 5;
    const bool hasL = tid > 0, hasR = tid < W_-1;
    const float4* x4 = (const float4*)x;

    if (bid < 256) {
        // ---------------- pass1: image k ----------------
        const int n = k;
        if (n >= N_) return;
        const int chunk = bid % CHUNKS;
        const int g     = bid / CHUNKS;
        const int h0    = chunk * ROWS;

        if (tid < 9*CPG_) {
            const int kk = tid / CPG_, cc = tid % CPG_;
            wsm[kk][cc] = wgt[kk*C_ + g*CPG_ + cc];
        }
        const unsigned sb0 = (unsigned)__cvta_generic_to_shared(&buf[0][0]);
        const unsigned sb1 = (unsigned)__cvta_generic_to_shared(&buf[1][0]);
        const unsigned sb2 = (unsigned)__cvta_generic_to_shared(&buf[2][0]);
        const size_t plane0 = (size_t)(n*C_ + g*CPG_) * HWQ;

        cpa_tile(sb0, x4 + plane0,       h0, tid); CP_COMMIT();
        cpa_tile(sb1, x4 + plane0 + HWQ, h0, tid); CP_COMMIT();

        float gs = 0.f, gs2 = 0.f;
        int bsel = 0;
        for (int cc = 0; cc < CPG_; ++cc) {
            CP_WAIT1();
            __syncthreads();
            if (cc + 2 < CPG_) {
                const unsigned sb = (bsel == 0) ? sb2 : (bsel == 1) ? sb0 : sb1;
                cpa_tile(sb, x4 + plane0 + (size_t)(cc+2)*HWQ, h0, tid);
            }
            CP_COMMIT();
            float wk[9];
            #pragma unroll
            for (int j = 0; j < 9; ++j) wk[j] = wsm[j][cc];
            const float* tile = (const float*)buf[bsel];
            CONV_STRIP(tile, wk, { gs += conv; gs2 = fmaf(conv, conv, gs2); });
            bsel = (bsel + 1 == 3) ? 0 : bsel + 1;
        }

        #pragma unroll
        for (int off = 16; off; off >>= 1) {
            gs  += __shfl_down_sync(0xffffffffu, gs,  off);
            gs2 += __shfl_down_sync(0xffffffffu, gs2, off);
        }
        if (lane == 0) { red[wid] = gs; red2[wid] = gs2; }
        __syncthreads();
        if (wid == 0) {
            float s  = (lane < 8) ? red[lane]  : 0.f;
            float s2 = (lane < 8) ? red2[lane] : 0.f;
            #pragma unroll
            for (int off = 4; off; off >>= 1) {
                s  += __shfl_down_sync(0xffffffffu, s,  off);
                s2 += __shfl_down_sync(0xffffffffu, s2, off);
            }
            if (lane == 0) {
                const int idx = ((n*G_ + g)*CHUNKS + chunk)*2;
                g_part[idx]   = s;
                g_part[idx+1] = s2;
            }
        }
    } else if (bid < 512) {
        // ---------------- pass2a: image k-1 (x is L2-resident) ----------------
        const int n = k - 1;
        if (n < 0 || n >= N_) return;
        const int sub   = bid - 256;
        const int chunk = sub % CHUNKS;
        const int g     = sub / CHUNKS;
        const int h0    = chunk * ROWS;

        if (tid < 9*CPG_) {
            const int kk = tid / CPG_, cc = tid % CPG_;
            wsm[kk][cc] = wgt[kk*C_ + g*CPG_ + cc];
        }
        // fold the stats reduce in here: 32 chunk-partials for this (n,g)
        if (tid < 32) {
            const int sg = (n*G_ + g)*CHUNKS;
            float s  = g_part[(sg + tid)*2];
            float s2 = g_part[(sg + tid)*2 + 1];
            #pragma unroll
            for (int off = 16; off; off >>= 1) {
                s  += __shfl_down_sync(0xffffffffu, s,  off);
                s2 += __shfl_down_sync(0xffffffffu, s2, off);
            }
            if (tid == 0) {
                const float inv = 1.0f / (float)(CPG_*H_*W_);
                const float m = s * inv;
                const float v = s2 * inv - m*m;
                s_stats[0] = m;
                s_stats[1] = rsqrtf(v + EPS_);
            }
        }

        const unsigned sb0 = (unsigned)__cvta_generic_to_shared(&buf[0][0]);
        const unsigned sb1 = (unsigned)__cvta_generic_to_shared(&buf[1][0]);
        const unsigned sb2 = (unsigned)__cvta_generic_to_shared(&buf[2][0]);
        const size_t plane0 = (size_t)(n*C_ + g*CPG_) * HWQ;

        cpa_tile(sb0, x4 + plane0,       h0, tid); CP_COMMIT();
        cpa_tile(sb1, x4 + plane0 + HWQ, h0, tid); CP_COMMIT();

        float acc[ROWS];
        #pragma unroll
        for (int r = 0; r < ROWS; ++r) acc[r] = 0.f;

        int bsel = 0;
        for (int cc = 0; cc < CPG_; ++cc) {
            CP_WAIT1();
            __syncthreads();                         // also makes s_stats visible
            const float mean = s_stats[0];
            const float rstd = s_stats[1];
            if (cc + 2 < CPG_) {
                const unsigned sb = (bsel == 0) ? sb2 : (bsel == 1) ? sb0 : sb1;
                cpa_tile(sb, x4 + plane0 + (size_t)(cc+2)*HWQ, h0, tid);
            }
            CP_COMMIT();
            float wk[9];
            #pragma unroll
            for (int j = 0; j < 9; ++j) wk[j] = wsm[j][cc];
            const float* tile = (const float*)buf[bsel];
            CONV_STRIP(tile, wk, {
                const float v = (conv - mean) * rstd;
                const float t = tanh_fast(v);
                // t in (-1,1) => clip(t+3,0,6) == t+3 exactly
                const float xr = fmaf(t * (1.0f/6.0f), t + 3.0f, conv);
                acc[r] += __expf(xr);
            });
            bsel = (bsel + 1 == 3) ? 0 : bsel + 1;
        }

        float* es = g_esum + ((size_t)(n*G_ + g)*H_ + h0) * W_;
        #pragma unroll
        for (int r = 0; r < ROWS; ++r) es[r*W_ + tid] = acc[r];
    } else {
        // ---------------- pass2b: image k-2 (esum is L2-resident) ----------------
        const int n = k - 2;
        if (n < 0) return;
        const int b2     = bid - 512;               // 0..511
        const int pixblk = b2 & 63;
        const int csel   = b2 >> 6;                 // 0..7
        const int p      = pixblk*NT + tid;         // quad within image
        const int c0     = csel * CHPB;

        const float4* e4 = (const float4*)g_esum;
        const size_t ebase = (size_t)n*G_*HWQ + p;
        float4 s = __ldg(&e4[ebase]);
        #pragma unroll
        for (int g = 1; g < G_; ++g) {
            const float4 v = __ldg(&e4[ebase + (size_t)g*HWQ]);
            s.x += v.x; s.y += v.y; s.z += v.z; s.w += v.w;
        }
        float4 L;
        L.x = __logf(s.x); L.y = __logf(s.y); L.z = __logf(s.z); L.w = __logf(s.w);

        float4* o4 = (float4*)out;
        const size_t obase = ((size_t)n*C_ + c0)*HWQ + p;
        #pragma unroll
        for (int c = 0; c < CHPB; ++c) __stcs(&o4[obase + (size_t)c*HWQ], L);
    }
}

extern "C" void kernel_launch(void* const* d_in, const int* in_sizes, int n_in,
                              void* d_out, int out_size) {
    const float* x   = (const float*)d_in[0];       // [8,64,256,256]
    const float* wgt = (const float*)d_in[1];       // [3,3,64]
    float* out = (float*)d_out;

    // 10-stage software pipeline over the 8 images:
    // stage k: pass1(k) | pass2a(k-1) | pass2b(k-2)
    for (int k = 0; k < N_ + 2; ++k)
        k_stage<<<1024, NT>>>(k, x, wgt, out);
}

// round 7
// speedup vs baseline: 1.2378x; 1.2378x over previous
#include <cuda_runtime.h>
#include <cstdint>

#define N_   8
#define C_   64
#define H_   256
#define W_   256
#define G_   8
#define CPG_ 8               // channels per group
#define ROWS 8               // rows per block strip
#define TR   (ROWS+2)        // tile rows incl. halo
#define CHUNKS (H_/ROWS)     // 32
#define EPS_ 1e-5f
#define NT   256
#define W4_  (W_/4)          // 64
#define TQ   (TR*W4_)        // 640 staging quads per tile
#define WP   264             // padded tile row width (floats): [0..2]pad [3]L-halo [4..259]data [260]R-halo [261..263]pad
#define HWQ  (H_*W_/4)       // 16384 quads per plane
#define CSPLIT 8
#define CHPB (C_/CSPLIT)     // 8 channels per pass2b block

// Static scratch (no runtime allocation)
__device__ float g_part[N_*G_*CHUNKS*2];
__device__ float g_esum[(size_t)N_*G_*H_*W_];      // per-(n,g) sum of exp (16.8 MB)

__device__ __forceinline__ float tanh_fast(float x) {
    float y;
    asm("tanh.approx.f32 %0, %1;" : "=f"(y) : "f"(x));
    return y;
}

#define CP_COMMIT() asm volatile("cp.async.commit_group;")
#define CP_WAIT1()  asm volatile("cp.async.wait_group 1;")

// Stage one (TR x W_) channel tile gmem -> padded smem rows via cp.async.cg.
// OOB rows zero-fill via src-size=0. dst = row*WP + 4 + 4q floats (16B aligned).
__device__ __forceinline__ void cpa_tile(unsigned sbase, const float4* __restrict__ xc4,
                                         int h0, int tid) {
    #pragma unroll
    for (int i = 0; i < 3; ++i) {
        const int idx = tid + i*NT;
        if (idx < TQ) {
            const int r = idx >> 6, q = idx & (W4_-1);
            const int h = h0 - 1 + r;
            const bool v = (h >= 0) && (h < H_);
            const float4* src = xc4 + (v ? (h*W4_ + q) : q);   // clamped (unread if sz=0)
            const int sz = v ? 16 : 0;
            const unsigned dst = sbase + (unsigned)(r*WP + 4 + 4*q)*4u;
            asm volatile("cp.async.cg.shared.global [%0], [%1], 16, %2;"
                         :: "r"(dst), "l"(src), "r"(sz));
        }
    }
}

// 3x3 depthwise conv, unconditional loads from the padded tile. SINK sees (r, conv).
#define CONV_STRIP(tile, wk, SINK)                                        \
    {                                                                     \
        const float* t0 = (tile) + 3 + tid;                               \
        float L0 = t0[0],      M0 = t0[1],      R0 = t0[2];               \
        float L1 = t0[WP],     M1 = t0[WP+1],   R1 = t0[WP+2];            \
        _Pragma("unroll")                                                 \
        for (int r = 0; r < ROWS; ++r) {                                  \
            const float* t2 = t0 + (r+2)*WP;                              \
            const float L2 = t2[0], M2 = t2[1], R2 = t2[2];               \
            float conv =        L0*wk[0];                                 \
            conv = fmaf(M0, wk[1], conv); conv = fmaf(R0, wk[2], conv);   \
            conv = fmaf(L1, wk[3], conv); conv = fmaf(M1, wk[4], conv);   \
            conv = fmaf(R1, wk[5], conv); conv = fmaf(L2, wk[6], conv);   \
            conv = fmaf(M2, wk[7], conv); conv = fmaf(R2, wk[8], conv);   \
            SINK;                                                         \
            L0=L1; M0=M1; R0=R1; L1=L2; M1=M2; R1=R2;                     \
        }                                                                 \
    }

// zero the halo columns (cols 3 and 260) of all TR rows in all 3 buffers, once
#define ZERO_HALOS(bufbase)                                               \
    if (tid < 3*TR*2) {                                                   \
        const int b = tid / (TR*2), rest = tid % (TR*2);                  \
        const int row = rest >> 1, col = (rest & 1) ? 260 : 3;            \
        (bufbase)[b*(TR*WP) + row*WP + col] = 0.f;                        \
    }

// ---------------- Pass 1: depthwise conv + per-(n,g,chunk) sum / sumsq ----------------
__global__ __launch_bounds__(NT, 6) void k_pass1(const float* __restrict__ x,
                                                 const float* __restrict__ wgt) {
    __shared__ float buf[3*TR*WP];                  // 3 x 10.3 KB padded tiles
    __shared__ float wsm[9][CPG_];
    __shared__ float red[8], red2[8];

    const int bid   = blockIdx.x;
    const int chunk = bid % CHUNKS;
    const int g     = (bid / CHUNKS) % G_;
    const int n     = bid / (CHUNKS * G_);
    const int h0    = chunk * ROWS;
    const int tid   = threadIdx.x;
    const int lane  = tid & 31, wid = tid >> 5;

    ZERO_HALOS(buf);
    if (tid >= 3*TR*2 && tid < 3*TR*2 + 9*CPG_) {
        const int t = tid - 3*TR*2;
        const int k = t / CPG_, cc = t % CPG_;
        wsm[k][cc] = wgt[k*C_ + g*CPG_ + cc];
    }

    const unsigned sb0 = (unsigned)__cvta_generic_to_shared(&buf[0]);
    const unsigned sb1 = sb0 + TR*WP*4u;
    const unsigned sb2 = sb1 + TR*WP*4u;

    const float4* x4 = (const float4*)x;
    const size_t plane0 = (size_t)(n*C_ + g*CPG_) * HWQ;

    cpa_tile(sb0, x4 + plane0,       h0, tid); CP_COMMIT();
    cpa_tile(sb1, x4 + plane0 + HWQ, h0, tid); CP_COMMIT();

    float gs = 0.f, gs2 = 0.f;
    int bsel = 0;
    for (int cc = 0; cc < CPG_; ++cc) {
        CP_WAIT1();
        __syncthreads();
        if (cc + 2 < CPG_) {
            const unsigned sb = (bsel == 0) ? sb2 : (bsel == 1) ? sb0 : sb1;
            cpa_tile(sb, x4 + plane0 + (size_t)(cc+2)*HWQ, h0, tid);
        }
        CP_COMMIT();

        float wk[9];
        #pragma unroll
        for (int j = 0; j < 9; ++j) wk[j] = wsm[j][cc];
        const float* tile = buf + bsel*(TR*WP);
        CONV_STRIP(tile, wk, { gs += conv; gs2 = fmaf(conv, conv, gs2); });
        bsel = (bsel + 1 == 3) ? 0 : bsel + 1;
    }

    #pragma unroll
    for (int off = 16; off; off >>= 1) {
        gs  += __shfl_down_sync(0xffffffffu, gs,  off);
        gs2 += __shfl_down_sync(0xffffffffu, gs2, off);
    }
    if (lane == 0) { red[wid] = gs; red2[wid] = gs2; }
    __syncthreads();
    if (wid == 0) {
        float s  = (lane < 8) ? red[lane]  : 0.f;
        float s2 = (lane < 8) ? red2[lane] : 0.f;
        #pragma unroll
        for (int off = 4; off; off >>= 1) {
            s  += __shfl_down_sync(0xffffffffu, s,  off);
            s2 += __shfl_down_sync(0xffffffffu, s2, off);
        }
        if (lane == 0) {
            const int idx = ((n*G_ + g)*CHUNKS + chunk)*2;
            g_part[idx]   = s;
            g_part[idx+1] = s2;
        }
    }
}

// ---------------- Pass 2a: conv recompute + norm/act/residual + group exp-sum ----------------
// Stats reduce (32 partials for this (n,g)) folded into the block prologue.
__global__ __launch_bounds__(NT, 6) void k_pass2a(const float* __restrict__ x,
                                                  const float* __restrict__ wgt) {
    __shared__ float buf[3*TR*WP];
    __shared__ float wsm[9][CPG_];
    __shared__ float s_stats[2];                    // mean, rstd

    const int bid   = (gridDim.x - 1) - blockIdx.x; // reversed vs pass1
    const int chunk = bid % CHUNKS;
    const int g     = (bid / CHUNKS) % G_;
    const int n     = bid / (CHUNKS * G_);
    const int h0    = chunk * ROWS;
    const int tid   = threadIdx.x;

    ZERO_HALOS(buf);
    if (tid >= 3*TR*2 && tid < 3*TR*2 + 9*CPG_) {
        const int t = tid - 3*TR*2;
        const int k = t / CPG_, cc = t % CPG_;
        wsm[k][cc] = wgt[k*C_ + g*CPG_ + cc];
    }
    // fold stats reduce: 32 chunk-partials for this (n,g) in one warp
    if (tid >= 224) {                               // warp 7
        const int l = tid - 224;
        const int sg = (n*G_ + g)*CHUNKS;
        float s  = g_part[(sg + l)*2];
        float s2 = g_part[(sg + l)*2 + 1];
        #pragma unroll
        for (int off = 16; off; off >>= 1) {
            s  += __shfl_down_sync(0xffffffffu, s,  off);
            s2 += __shfl_down_sync(0xffffffffu, s2, off);
        }
        if (l == 0) {
            const float inv = 1.0f / (float)(CPG_*H_*W_);
            const float m = s * inv;
            const float v = s2 * inv - m*m;
            s_stats[0] = m;
            s_stats[1] = rsqrtf(v + EPS_);
        }
    }

    const unsigned sb0 = (unsigned)__cvta_generic_to_shared(&buf[0]);
    const unsigned sb1 = sb0 + TR*WP*4u;
    const unsigned sb2 = sb1 + TR*WP*4u;

    const float4* x4 = (const float4*)x;
    const size_t plane0 = (size_t)(n*C_ + g*CPG_) * HWQ;

    cpa_tile(sb0, x4 + plane0,       h0, tid); CP_COMMIT();
    cpa_tile(sb1, x4 + plane0 + HWQ, h0, tid); CP_COMMIT();

    float acc[ROWS];
    #pragma unroll
    for (int r = 0; r < ROWS; ++r) acc[r] = 0.f;

    int bsel = 0;
    for (int cc = 0; cc < CPG_; ++cc) {
        CP_WAIT1();
        __syncthreads();                            // also publishes s_stats
        const float mean = s_stats[0];
        const float rstd = s_stats[1];
        if (cc + 2 < CPG_) {
            const unsigned sb = (bsel == 0) ? sb2 : (bsel == 1) ? sb0 : sb1;
            cpa_tile(sb, x4 + plane0 + (size_t)(cc+2)*HWQ, h0, tid);
        }
        CP_COMMIT();

        float wk[9];
        #pragma unroll
        for (int j = 0; j < 9; ++j) wk[j] = wsm[j][cc];
        const float* tile = buf + bsel*(TR*WP);
        CONV_STRIP(tile, wk, {
            const float v = (conv - mean) * rstd;
            const float t = tanh_fast(v);
            // t in (-1,1) => clip(t+3,0,6) == t+3 exactly
            const float xr = fmaf(t * (1.0f/6.0f), t + 3.0f, conv);
            acc[r] += __expf(xr);
        });
        bsel = (bsel + 1 == 3) ? 0 : bsel + 1;
    }

    float* es = g_esum + ((size_t)(n*G_ + g)*H_ + h0) * W_;
    #pragma unroll
    for (int r = 0; r < ROWS; ++r) es[r*W_ + tid] = acc[r];
}

// ---------------- Pass 2b: combine groups, log, broadcast 8 channels/block ----------------
__global__ __launch_bounds__(NT) void k_pass2b(float* __restrict__ out) {
    const int p   = blockIdx.x * NT + threadIdx.x;  // quad index
    const int n   = p >> 14;                        // / HWQ
    const int pix = p & (HWQ - 1);
    const int c0  = blockIdx.y * CHPB;

    const float4* e4 = (const float4*)g_esum;
    const size_t ebase = (size_t)n*G_*HWQ + pix;
    float4 s = __ldg(&e4[ebase]);
    #pragma unroll
    for (int g = 1; g < G_; ++g) {
        const float4 v = __ldg(&e4[ebase + (size_t)g*HWQ]);
        s.x += v.x; s.y += v.y; s.z += v.z; s.w += v.w;
    }
    float4 L;
    L.x = __logf(s.x); L.y = __logf(s.y); L.z = __logf(s.z); L.w = __logf(s.w);

    float4* o4 = (float4*)out;
    const size_t obase = (size_t)n*C_*HWQ + (size_t)c0*HWQ + pix;
    #pragma unroll
    for (int c = 0; c < CHPB; ++c) __stcs(&o4[obase + (size_t)c*HWQ], L);
}

extern "C" void kernel_launch(void* const* d_in, const int* in_sizes, int n_in,
                              void* d_out, int out_size) {
    const float* x   = (const float*)d_in[0];       // [8,64,256,256]
    const float* wgt = (const float*)d_in[1];       // [3,3,64]
    float* out = (float*)d_out;

    k_pass1 <<<N_*G_*CHUNKS, NT>>>(x, wgt);
    k_pass2a<<<N_*G_*CHUNKS, NT>>>(x, wgt);
    k_pass2b<<<dim3((N_*HWQ)/NT, CSPLIT), NT>>>(out);
}

// round 9
// speedup vs baseline: 1.3643x; 1.1022x over previous
#include <cuda_runtime.h>
#include <cstdint>

#define N_   8
#define C_   64
#define H_   256
#define W_   256
#define G_   8
#define CPG_ 8               // channels per group
#define ROWS 8               // rows per block strip
#define TR   (ROWS+2)        // tile rows incl. halo
#define CHUNKS (H_/ROWS)     // 32
#define EPS_ 1e-5f
#define NT   128             // 64 col-groups x 2 row-groups
#define W4_  (W_/4)          // 64
#define TQ   (TR*W4_)        // 640 staging quads (= 5*NT exactly)
#define WP   264             // padded row width: col3 = L-halo, cols4..259 data, col260 = R-halo
#define BUFF (TR*WP)         // floats per tile buffer
#define HWQ  (H_*W_/4)
#define CSPLIT 8
#define CHPB (C_/CSPLIT)

typedef unsigned long long u64;

// Static scratch (no runtime allocation)
__device__ float g_part[N_*G_*CHUNKS*2];
__device__ float g_esum[(size_t)N_*G_*H_*W_];      // per-(n,g) sum of exp

// ---- f32x2 packed helpers (sm_100+) ----
__device__ __forceinline__ u64 pack2(float lo, float hi) {
    u64 r; asm("mov.b64 %0,{%1,%2};" : "=l"(r) : "f"(lo), "f"(hi)); return r;
}
__device__ __forceinline__ void unpack2(u64 v, float& lo, float& hi) {
    asm("mov.b64 {%0,%1},%2;" : "=f"(lo), "=f"(hi) : "l"(v));
}
__device__ __forceinline__ u64 fma2(u64 a, u64 b, u64 c) {
    u64 d; asm("fma.rn.f32x2 %0,%1,%2,%3;" : "=l"(d) : "l"(a), "l"(b), "l"(c)); return d;
}
__device__ __forceinline__ u64 add2(u64 a, u64 b) {
    u64 d; asm("add.rn.f32x2 %0,%1,%2;" : "=l"(d) : "l"(a), "l"(b)); return d;
}
__device__ __forceinline__ u64 mul2(u64 a, u64 b) {
    u64 d; asm("mul.rn.f32x2 %0,%1,%2;" : "=l"(d) : "l"(a), "l"(b)); return d;
}
__device__ __forceinline__ float tanh_fast(float x) {
    float y; asm("tanh.approx.f32 %0,%1;" : "=f"(y) : "f"(x)); return y;
}
__device__ __forceinline__ float ex2_fast(float x) {
    float y; asm("ex2.approx.f32 %0,%1;" : "=f"(y) : "f"(x)); return y;
}

#define CP_COMMIT() asm volatile("cp.async.commit_group;")
#define CP_WAIT1()  asm volatile("cp.async.wait_group 1;")

// Stage one (TR x W_) channel tile gmem -> padded smem rows via cp.async.cg.
__device__ __forceinline__ void cpa_tile(unsigned sbase, const float4* __restrict__ xc4,
                                         int h0, int tid) {
    #pragma unroll
    for (int i = 0; i < 5; ++i) {
        const int idx = tid + i*NT;                 // 5*128 = 640 = TQ exactly
        const int r = idx >> 6, q = idx & (W4_-1);
        const int h = h0 - 1 + r;
        const bool v = (h >= 0) && (h < H_);
        const float4* src = xc4 + (v ? (h*W4_ + q) : q);
        const int sz = v ? 16 : 0;
        const unsigned dst = sbase + (unsigned)(r*WP + 4 + 4*q)*4u;
        asm volatile("cp.async.cg.shared.global [%0], [%1], 16, %2;"
                     :: "r"(dst), "l"(src), "r"(sz));
    }
}

// 5 shifted operand pairs for one tile row, covering 4 pixels (2 f32x2 pairs)
struct RowP { u64 P0, P1, P2, P3, P4; };

__device__ __forceinline__ RowP load_row(const float* rb) {   // rb -> first data col of this thread
    RowP p;
    const float  L = rb[-1];
    const float4 M = *(const float4*)rb;            // LDS.128, 16B aligned
    const float  R = rb[4];
    p.P0 = pack2(L,   M.x); p.P1 = pack2(M.x, M.y); p.P2 = pack2(M.y, M.z);
    p.P3 = pack2(M.z, M.w); p.P4 = pack2(M.w, R);
    return p;
}

// packed 3x3 conv: pair A = pixels {0,1}, pair B = pixels {2,3}
#define CONV2(r0, r1, r2, wkp, cA, cB)                                              \
    cA = mul2(r0.P0, wkp[0]); cA = fma2(r0.P1, wkp[1], cA); cA = fma2(r0.P2, wkp[2], cA); \
    cA = fma2(r1.P0, wkp[3], cA); cA = fma2(r1.P1, wkp[4], cA); cA = fma2(r1.P2, wkp[5], cA); \
    cA = fma2(r2.P0, wkp[6], cA); cA = fma2(r2.P1, wkp[7], cA); cA = fma2(r2.P2, wkp[8], cA); \
    cB = mul2(r0.P2, wkp[0]); cB = fma2(r0.P3, wkp[1], cB); cB = fma2(r0.P4, wkp[2], cB); \
    cB = fma2(r1.P2, wkp[3], cB); cB = fma2(r1.P3, wkp[4], cB); cB = fma2(r1.P4, wkp[5], cB); \
    cB = fma2(r2.P2, wkp[6], cB); cB = fma2(r2.P3, wkp[7], cB); cB = fma2(r2.P4, wkp[8], cB);

// zero halo columns (cols 3 and 260) of all TR rows in all 3 buffers
#define ZERO_HALOS(bufbase)                                               \
    if (tid < 3*TR*2) {                                                   \
        const int b = tid / (TR*2), rest = tid % (TR*2);                  \
        const int row = rest >> 1, col = (rest & 1) ? 260 : 3;            \
        (bufbase)[b*BUFF + row*WP + col] = 0.f;                           \
    }

// load the 9 x CPG_ weights as duplicated float2 (FIX: all 72 entries covered)
#define LOAD_WEIGHTS()                                                    \
    if (tid < 9*CPG_) {                                                   \
        const int j = tid / CPG_, cc = tid % CPG_;                        \
        const float w = wgt[j*C_ + g*CPG_ + cc];                          \
        wsm2[j][cc] = make_float2(w, w);                                  \
    }

// ---------------- Pass 1: depthwise conv + per-(n,g,chunk) sum / sumsq ----------------
__global__ __launch_bounds__(NT) void k_pass1(const float* __restrict__ x,
                                              const float* __restrict__ wgt) {
    __shared__ __align__(16) float buf[3*BUFF];
    __shared__ float2 wsm2[9][CPG_];
    __shared__ float  red[4], red2[4];

    const int bid   = blockIdx.x;
    const int chunk = bid % CHUNKS;
    const int g     = (bid / CHUNKS) % G_;
    const int n     = bid / (CHUNKS * G_);
    const int h0    = chunk * ROWS;
    const int tid   = threadIdx.x;
    const int tx    = tid & 63;                     // col group: cols 4tx..4tx+3
    const int ty    = tid >> 6;                     // row group: rows 4ty..4ty+3
    const int lane  = tid & 31, wid = tid >> 5;

    ZERO_HALOS(buf);
    LOAD_WEIGHTS();

    const unsigned sb0 = (unsigned)__cvta_generic_to_shared(&buf[0]);
    const float4* x4 = (const float4*)x;
    const size_t plane0 = (size_t)(n*C_ + g*CPG_) * HWQ;

    cpa_tile(sb0,                    x4 + plane0,       h0, tid); CP_COMMIT();
    cpa_tile(sb0 + (unsigned)BUFF*4, x4 + plane0 + HWQ, h0, tid); CP_COMMIT();

    u64 gsP = 0, gs2P = 0;                          // packed (0.f,0.f)
    int bsel = 0;
    for (int cc = 0; cc < CPG_; ++cc) {
        CP_WAIT1();
        __syncthreads();
        if (cc + 2 < CPG_) {
            const int nb = (bsel + 2 >= 3) ? bsel - 1 : bsel + 2;
            cpa_tile(sb0 + (unsigned)(nb*BUFF)*4, x4 + plane0 + (size_t)(cc+2)*HWQ, h0, tid);
        }
        CP_COMMIT();

        u64 wkp[9];
        #pragma unroll
        for (int j = 0; j < 9; ++j) wkp[j] = *(const u64*)&wsm2[j][cc];

        const float* tb = buf + bsel*BUFF + 4 + 4*tx;
        RowP r0 = load_row(tb + (4*ty+0)*WP);
        RowP r1 = load_row(tb + (4*ty+1)*WP);
        #pragma unroll
        for (int rr = 0; rr < 4; ++rr) {
            RowP r2 = load_row(tb + (4*ty+2+rr)*WP);
            u64 cA, cB;
            CONV2(r0, r1, r2, wkp, cA, cB);
            gsP  = add2(gsP, add2(cA, cB));
            gs2P = fma2(cA, cA, gs2P);
            gs2P = fma2(cB, cB, gs2P);
            r0 = r1; r1 = r2;
        }
        bsel = (bsel + 1 == 3) ? 0 : bsel + 1;
    }

    float a, b, gs, gs2;
    unpack2(gsP,  a, b); gs  = a + b;
    unpack2(gs2P, a, b); gs2 = a + b;
    #pragma unroll
    for (int off = 16; off; off >>= 1) {
        gs  += __shfl_down_sync(0xffffffffu, gs,  off);
        gs2 += __shfl_down_sync(0xffffffffu, gs2, off);
    }
    if (lane == 0) { red[wid] = gs; red2[wid] = gs2; }
    __syncthreads();
    if (tid == 0) {
        float s = red[0] + red[1] + red[2] + red[3];
        float s2 = red2[0] + red2[1] + red2[2] + red2[3];
        const int idx = ((n*G_ + g)*CHUNKS + chunk)*2;
        g_part[idx]   = s;
        g_part[idx+1] = s2;
    }
}

// ---------------- Pass 2a: conv recompute + norm/act/residual + group exp-sum ----------------
__global__ __launch_bounds__(NT) void k_pass2a(const float* __restrict__ x,
                                               const float* __restrict__ wgt) {
    __shared__ __align__(16) float buf[3*BUFF];
    __shared__ float2 wsm2[9][CPG_];
    __shared__ float  s_stats[2];

    const int bid   = (gridDim.x - 1) - blockIdx.x;
    const int chunk = bid % CHUNKS;
    const int g     = (bid / CHUNKS) % G_;
    const int n     = bid / (CHUNKS * G_);
    const int h0    = chunk * ROWS;
    const int tid   = threadIdx.x;
    const int tx    = tid & 63;
    const int ty    = tid >> 6;

    ZERO_HALOS(buf);
    LOAD_WEIGHTS();
    // fold stats reduce: 32 chunk-partials for this (n,g), warp 3
    if (tid >= 96) {
        const int l = tid - 96;
        const int sg = (n*G_ + g)*CHUNKS;
        float s  = g_part[(sg + l)*2];
        float s2 = g_part[(sg + l)*2 + 1];
        #pragma unroll
        for (int off = 16; off; off >>= 1) {
            s  += __shfl_down_sync(0xffffffffu, s,  off);
            s2 += __shfl_down_sync(0xffffffffu, s2, off);
        }
        if (l == 0) {
            const float inv = 1.0f / (float)(CPG_*H_*W_);
            const float m = s * inv;
            const float v = s2 * inv - m*m;
            s_stats[0] = m;
            s_stats[1] = rsqrtf(v + EPS_);
        }
    }

    const unsigned sb0 = (unsigned)__cvta_generic_to_shared(&buf[0]);
    const float4* x4 = (const float4*)x;
    const size_t plane0 = (size_t)(n*C_ + g*CPG_) * HWQ;

    cpa_tile(sb0,                    x4 + plane0,       h0, tid); CP_COMMIT();
    cpa_tile(sb0 + (unsigned)BUFF*4, x4 + plane0 + HWQ, h0, tid); CP_COMMIT();

    u64 acc[8];                                     // 4 rows x {A,B} pairs
    #pragma unroll
    for (int i = 0; i < 8; ++i) acc[i] = 0;

    const u64 threeP  = pack2(3.0f, 3.0f);
    const u64 sixthP  = pack2(1.0f/6.0f, 1.0f/6.0f);
    const u64 log2eP  = pack2(1.4426950408889634f, 1.4426950408889634f);

    int bsel = 0;
    for (int cc = 0; cc < CPG_; ++cc) {
        CP_WAIT1();
        __syncthreads();                            // also publishes s_stats
        const float mean = s_stats[0];
        const float rstd = s_stats[1];
        const u64 rstdP = pack2(rstd, rstd);
        const u64 nmrP  = pack2(-mean*rstd, -mean*rstd);
        if (cc + 2 < CPG_) {
            const int nb = (bsel + 2 >= 3) ? bsel - 1 : bsel + 2;
            cpa_tile(sb0 + (unsigned)(nb*BUFF)*4, x4 + plane0 + (size_t)(cc+2)*HWQ, h0, tid);
        }
        CP_COMMIT();

        u64 wkp[9];
        #pragma unroll
        for (int j = 0; j < 9; ++j) wkp[j] = *(const u64*)&wsm2[j][cc];

        const float* tb = buf + bsel*BUFF + 4 + 4*tx;
        RowP r0 = load_row(tb + (4*ty+0)*WP);
        RowP r1 = load_row(tb + (4*ty+1)*WP);
        #pragma unroll
        for (int rr = 0; rr < 4; ++rr) {
            RowP r2 = load_row(tb + (4*ty+2+rr)*WP);
            u64 cv[2];
            CONV2(r0, r1, r2, wkp, cv[0], cv[1]);
            #pragma unroll
            for (int h = 0; h < 2; ++h) {
                const u64 vP = fma2(cv[h], rstdP, nmrP);   // (conv-mean)*rstd
                float v0, v1; unpack2(vP, v0, v1);
                const u64 tP = pack2(tanh_fast(v0), tanh_fast(v1));
                // t in (-1,1) => clip(t+3,0,6) == t+3: xr = conv + t*(t+3)/6
                const u64 xrP = fma2(mul2(tP, sixthP), add2(tP, threeP), cv[h]);
                const u64 aP  = mul2(xrP, log2eP);
                float a0, a1; unpack2(aP, a0, a1);
                const u64 eP = pack2(ex2_fast(a0), ex2_fast(a1));
                acc[rr*2+h] = add2(acc[rr*2+h], eP);
            }
            r0 = r1; r1 = r2;
        }
        bsel = (bsel + 1 == 3) ? 0 : bsel + 1;
    }

    float* es = g_esum + ((size_t)(n*G_ + g)*H_ + h0 + 4*ty)*W_ + 4*tx;
    #pragma unroll
    for (int rr = 0; rr < 4; ++rr) {
        float4 o;
        unpack2(acc[rr*2+0], o.x, o.y);
        unpack2(acc[rr*2+1], o.z, o.w);
        *(float4*)(es + rr*W_) = o;
    }
}

// ---------------- Pass 2b: combine groups, log, broadcast 8 channels/block ----------------
__global__ __launch_bounds__(256) void k_pass2b(float* __restrict__ out) {
    const int p   = blockIdx.x * 256 + threadIdx.x;
    const int n   = p >> 14;
    const int pix = p & (HWQ - 1);
    const int c0  = blockIdx.y * CHPB;

    const float4* e4 = (const float4*)g_esum;
    const size_t ebase = (size_t)n*G_*HWQ + pix;
    float4 s = __ldg(&e4[ebase]);
    #pragma unroll
    for (int g = 1; g < G_; ++g) {
        const float4 v = __ldg(&e4[ebase + (size_t)g*HWQ]);
        s.x += v.x; s.y += v.y; s.z += v.z; s.w += v.w;
    }
    float4 L;
    L.x = __logf(s.x); L.y = __logf(s.y); L.z = __logf(s.z); L.w = __logf(s.w);

    float4* o4 = (float4*)out;
    const size_t obase = (size_t)n*C_*HWQ + (size_t)c0*HWQ + pix;
    #pragma unroll
    for (int c = 0; c < CHPB; ++c) __stcs(&o4[obase + (size_t)c*HWQ], L);
}

extern "C" void kernel_launch(void* const* d_in, const int* in_sizes, int n_in,
                              void* d_out, int out_size) {
    const float* x   = (const float*)d_in[0];       // [8,64,256,256]
    const float* wgt = (const float*)d_in[1];       // [3,3,64]
    float* out = (float*)d_out;

    k_pass1 <<<N_*G_*CHUNKS, NT>>>(x, wgt);
    k_pass2a<<<N_*G_*CHUNKS, NT>>>(x, wgt);
    k_pass2b<<<dim3((N_*HWQ)/256, CSPLIT), 256>>>(out);
}